// round 1
// baseline (speedup 1.0000x reference)
#include <cuda_runtime.h>

#define Bn 32
#define Tn 1500
#define En 512
#define An 512
#define Cn 10
#define Kn 100
#define KW 201
#define On 512
#define NA_CHUNKS 4
#define TC_CHUNKS 8

// ---------------- scratch (no allocation allowed) ----------------
__device__ float g_decproj[Bn * An];                 // dec projection + b_enc
__device__ float g_attc[Bn * Tn * Cn];               // conv features [b][t][c]
__device__ float g_epart[Bn * Tn * NA_CHUNKS];       // partial e per A-chunk
__device__ float g_cpart[Bn * TC_CHUNKS * En];       // partial context per T-chunk

// ---------------- helpers ----------------
__device__ __forceinline__ unsigned long long dup2(float x) {
    unsigned u = __float_as_uint(x);
    return ((unsigned long long)u << 32) | (unsigned long long)u;
}

__device__ __forceinline__ void ffma2(unsigned long long& d,
                                      unsigned long long a,
                                      unsigned long long b) {
    // packed fp32x2 FMA (sm_10x): d.lo += a.lo*b.lo ; d.hi += a.hi*b.hi
    asm("fma.rn.f32x2 %0, %1, %2, %0;" : "+l"(d) : "l"(a), "l"(b));
}

__device__ __forceinline__ float fast_tanh(float x) {
    // tanh(x) = 1 - 2/(e^{2x}+1); exact at +-inf saturation, ~1e-7 abs err
    float e = __expf(2.0f * x);
    return 1.0f - 2.0f / (e + 1.0f);
}

// ---------------- K1: dec_proj = dec_z @ W_dec + b_enc ----------------
__global__ void k_dec(const float* __restrict__ dec_z,
                      const float* __restrict__ W_dec,
                      const float* __restrict__ b_enc) {
    int b = blockIdx.x;
    __shared__ float z[512];
    for (int i = threadIdx.x; i < 512; i += 256) z[i] = dec_z[b * 512 + i];
    __syncthreads();
    for (int a = threadIdx.x; a < An; a += 256) {
        float acc = b_enc[a];
#pragma unroll 8
        for (int k = 0; k < 512; k++)
            acc = fmaf(z[k], W_dec[(size_t)k * An + a], acc);
        g_decproj[b * An + a] = acc;
    }
}

// ---------------- K2: location conv -> attc[b][t][c] ----------------
__global__ void k_conv(const float* __restrict__ att_prev,
                       const float* __restrict__ conv_w) {
    int b = blockIdx.y;
    int t0 = blockIdx.x * 128;
    int tid = threadIdx.x;
    __shared__ float cw[Cn * KW];
    __shared__ float xs[128 + 2 * Kn];
    for (int i = tid; i < Cn * KW; i += 128) cw[i] = conv_w[i];
    for (int i = tid; i < 128 + 2 * Kn; i += 128) {
        int tt = t0 - Kn + i;
        xs[i] = (tt >= 0 && tt < Tn) ? att_prev[b * Tn + tt] : 0.0f;
    }
    __syncthreads();
    int t = t0 + tid;
    if (t < Tn) {
#pragma unroll
        for (int c = 0; c < Cn; c++) {
            float acc = 0.0f;
#pragma unroll 8
            for (int h = 0; h < KW; h++)
                acc = fmaf(cw[c * KW + h], xs[tid + h], acc);
            g_attc[((size_t)b * Tn + t) * Cn + c] = acc;
        }
    }
}

// ---------------- K3: fused GEMM (enc@W_enc) + epilogue -> e partials ----
// Tile: 64 rows(t) x 128 cols(a), BK=16, 256 threads, FFMA2 inner loop.
__global__ __launch_bounds__(256, 2) void k_gemm_e(
    const float* __restrict__ enc, const float* __restrict__ W_enc,
    const float* __restrict__ W_att, const float* __restrict__ gvec) {
    __shared__ unsigned long long As2[16][65];  // duplicated fp32 pairs, padded
    __shared__ float Bs[16][128];
    __shared__ float decb[128];
    __shared__ float gv[128];
    __shared__ float wat[Cn][128];
    __shared__ float atc[64][Cn];

    int tid = threadIdx.x;
    int b = blockIdx.z, mt = blockIdx.x, na = blockIdx.y;
    int t0 = mt * 64, n0 = na * 128;
    int ty = tid >> 4, tx = tid & 15;

    unsigned long long acc[4][4];
#pragma unroll
    for (int r = 0; r < 4; r++)
#pragma unroll
        for (int j = 0; j < 4; j++) acc[r][j] = 0ull;

    const float* encb = enc + ((size_t)b * Tn + t0) * En;
    int lm = tid >> 2, lq = tid & 3;
    bool mvalid = (t0 + lm) < Tn;
    const float* aptr = encb + (size_t)lm * En + lq * 4;
    int bk = tid >> 4, bc = tid & 15;
    const float* bptr = W_enc + (size_t)bk * An + n0 + bc * 4;

    for (int kb = 0; kb < En; kb += 16) {
        float4 av = make_float4(0.f, 0.f, 0.f, 0.f);
        if (mvalid) av = *(const float4*)(aptr + kb);
        float4 bv0 = *(const float4*)(bptr + (size_t)kb * An);
        float4 bv1 = *(const float4*)(bptr + (size_t)kb * An + 64);
        __syncthreads();
        As2[lq * 4 + 0][lm] = dup2(av.x);
        As2[lq * 4 + 1][lm] = dup2(av.y);
        As2[lq * 4 + 2][lm] = dup2(av.z);
        As2[lq * 4 + 3][lm] = dup2(av.w);
        *(float4*)&Bs[bk][bc * 4] = bv0;
        *(float4*)&Bs[bk][64 + bc * 4] = bv1;
        __syncthreads();
#pragma unroll
        for (int k = 0; k < 16; k++) {
            unsigned long long a2[4], b2[4];
#pragma unroll
            for (int r = 0; r < 4; r++) a2[r] = As2[k][ty + 16 * r];
#pragma unroll
            for (int j = 0; j < 4; j++)
                b2[j] = *(const unsigned long long*)&Bs[k][tx * 2 + 32 * j];
#pragma unroll
            for (int r = 0; r < 4; r++)
#pragma unroll
                for (int j = 0; j < 4; j++) ffma2(acc[r][j], a2[r], b2[j]);
        }
    }
    __syncthreads();

    // epilogue staging
    for (int i = tid; i < 128; i += 256) {
        decb[i] = g_decproj[b * An + n0 + i];
        gv[i] = gvec[n0 + i];
    }
    for (int i = tid; i < Cn * 128; i += 256) {
        int c = i >> 7, n = i & 127;
        wat[c][n] = W_att[c * An + n0 + n];
    }
    for (int i = tid; i < 64 * Cn; i += 256) {
        int m = i / Cn, c = i % Cn;
        int t = t0 + m;
        atc[m][c] = (t < Tn) ? g_attc[((size_t)b * Tn + t) * Cn + c] : 0.0f;
    }
    __syncthreads();

    float esum[4];
#pragma unroll
    for (int r = 0; r < 4; r++) {
        int m = ty + 16 * r;
        float ac[Cn];
#pragma unroll
        for (int c = 0; c < Cn; c++) ac[c] = atc[m][c];
        float s = 0.0f;
#pragma unroll
        for (int j = 0; j < 4; j++) {
            int n = tx * 2 + 32 * j;
            float2 av = *reinterpret_cast<float2*>(&acc[r][j]);
            float v0 = av.x + decb[n];
            float v1 = av.y + decb[n + 1];
#pragma unroll
            for (int c = 0; c < Cn; c++) {
                v0 = fmaf(ac[c], wat[c][n], v0);
                v1 = fmaf(ac[c], wat[c][n + 1], v1);
            }
            s = fmaf(fast_tanh(v0), gv[n], s);
            s = fmaf(fast_tanh(v1), gv[n + 1], s);
        }
        esum[r] = s;
    }
#pragma unroll
    for (int r = 0; r < 4; r++) {
        float s = esum[r];
#pragma unroll
        for (int o = 8; o > 0; o >>= 1)
            s += __shfl_xor_sync(0xffffffffu, s, o, 16);
        int t = t0 + ty + 16 * r;
        if (tx == 0 && t < Tn)
            g_epart[((size_t)b * Tn + t) * NA_CHUNKS + na] = s;
    }
}

// ---------------- K4: softmax(2*e) -> w (written straight into d_out) ----
__global__ void k_softmax(float* __restrict__ w_out) {
    int b = blockIdx.x, tid = threadIdx.x;
    __shared__ float es[Tn];
    __shared__ float red[256];
    for (int t = tid; t < Tn; t += 256) {
        const float* p = &g_epart[((size_t)b * Tn + t) * NA_CHUNKS];
        es[t] = 2.0f * (p[0] + p[1] + p[2] + p[3]);
    }
    __syncthreads();
    float m = -1e30f;
    for (int t = tid; t < Tn; t += 256) m = fmaxf(m, es[t]);
    red[tid] = m;
    __syncthreads();
    for (int s = 128; s > 0; s >>= 1) {
        if (tid < s) red[tid] = fmaxf(red[tid], red[tid + s]);
        __syncthreads();
    }
    m = red[0];
    __syncthreads();
    float sum = 0.0f;
    for (int t = tid; t < Tn; t += 256) {
        float ex = __expf(es[t] - m);
        es[t] = ex;
        sum += ex;
    }
    red[tid] = sum;
    __syncthreads();
    for (int s = 128; s > 0; s >>= 1) {
        if (tid < s) red[tid] += red[tid + s];
        __syncthreads();
    }
    float inv = 1.0f / red[0];
    for (int t = tid; t < Tn; t += 256) w_out[b * Tn + t] = es[t] * inv;
}

// ---------------- K5: context partials c = w @ enc_pad ----------------
__global__ void k_ctx(const float* __restrict__ enc,
                      const float* __restrict__ w) {
    int b = blockIdx.y, tc = blockIdx.x, e = threadIdx.x;
    const float* encb = enc + (size_t)b * Tn * En;
    const float* wb = w + b * Tn;
    int t0 = tc * 188;
    int t1 = t0 + 188;
    if (t1 > Tn) t1 = Tn;
    float acc = 0.0f;
#pragma unroll 4
    for (int t = t0; t < t1; t++)
        acc = fmaf(wb[t], encb[(size_t)t * En + e], acc);
    g_cpart[((size_t)b * TC_CHUNKS + tc) * En + e] = acc;
}

// ---------------- K6: out_c = c @ W_o + b_o ----------------
__global__ void k_out(const float* __restrict__ W_o,
                      const float* __restrict__ b_o,
                      float* __restrict__ out_c) {
    int b = blockIdx.y;
    int o = blockIdx.x * 128 + threadIdx.x;
    __shared__ float cs[En];
    for (int e = threadIdx.x; e < En; e += 128) {
        float s = 0.0f;
#pragma unroll
        for (int ch = 0; ch < TC_CHUNKS; ch++)
            s += g_cpart[((size_t)b * TC_CHUNKS + ch) * En + e];
        cs[e] = s;
    }
    __syncthreads();
    float acc = b_o[o];
#pragma unroll 8
    for (int e = 0; e < En; e++)
        acc = fmaf(cs[e], W_o[(size_t)e * On + o], acc);
    out_c[(size_t)b * On + o] = acc;
}

// ---------------- launch ----------------
extern "C" void kernel_launch(void* const* d_in, const int* in_sizes, int n_in,
                              void* d_out, int out_size) {
    const float* enc      = (const float*)d_in[0];
    // d_in[1] = enc_len (unused by the reference)
    const float* dec_z    = (const float*)d_in[2];
    const float* att_prev = (const float*)d_in[3];
    const float* W_enc    = (const float*)d_in[4];
    const float* b_enc    = (const float*)d_in[5];
    const float* W_dec    = (const float*)d_in[6];
    const float* W_att    = (const float*)d_in[7];
    const float* conv_w   = (const float*)d_in[8];
    const float* gvec     = (const float*)d_in[9];
    const float* W_o      = (const float*)d_in[10];
    const float* b_o      = (const float*)d_in[11];

    float* out   = (float*)d_out;
    float* out_c = out;              // [B, O]
    float* out_w = out + Bn * On;    // [B, T]

    k_dec<<<Bn, 256>>>(dec_z, W_dec, b_enc);
    k_conv<<<dim3((Tn + 127) / 128, Bn), 128>>>(att_prev, conv_w);
    k_gemm_e<<<dim3((Tn + 63) / 64, NA_CHUNKS, Bn), 256>>>(enc, W_enc, W_att, gvec);
    k_softmax<<<Bn, 256>>>(out_w);
    k_ctx<<<dim3(TC_CHUNKS, Bn), 512>>>(enc, out_w);
    k_out<<<dim3(On / 128, Bn), 128>>>(W_o, b_o, out_c);
}

// round 3
// speedup vs baseline: 1.7681x; 1.7681x over previous
#include <cuda_runtime.h>
#include <cuda_fp16.h>
#include <cstdint>

#define Bn 32
#define Tn 1500
#define En 512
#define An 512
#define Cn 10
#define KW 201
#define On 512
#define NA_CHUNKS 4
#define TC_CHUNKS 15

#define MT 128
#define NTC 128            // CTA n-tile
#define BK 32
#define NCHUNK 16          // 512/32
#define MTILES 375
#define NTILES 4

#define PITCH 40           // fp16 elems per smem row (80 bytes)
#define TILE_BYTES 10240   // 128 * 80
#define OFF_AH 0
#define OFF_AL 10240
#define OFF_BH 20480
#define OFF_BL 30720
#define STAGE_BYTES 40960
#define NSTAGES 3
#define SMEM_GEMM (NSTAGES * STAGE_BYTES)

// ---------------- scratch ----------------
__device__ float g_decproj[Bn * An];
__device__ float g_attc[Bn * Tn * Cn];
__device__ float g_epart[Bn * Tn * NA_CHUNKS];
__device__ float g_cpart[Bn * TC_CHUNKS * En];
__device__ __half g_ahi[(size_t)Bn * Tn * En];
__device__ __half g_alo[(size_t)Bn * Tn * En];
__device__ __half g_bhi[An * En];   // [n][k]
__device__ __half g_blo[An * En];

// ---------------- helpers ----------------
__device__ __forceinline__ uint32_t smem_u32(const void* p) {
    uint32_t a;
    asm("{ .reg .u64 t; cvta.to.shared.u64 t, %1; cvt.u32.u64 %0, t; }" : "=r"(a) : "l"(p));
    return a;
}

__device__ __forceinline__ void cp_async16(uint32_t dst, const void* src) {
    asm volatile("cp.async.cg.shared.global [%0], [%1], 16;" :: "r"(dst), "l"(src));
}
__device__ __forceinline__ void cp_commit() {
    asm volatile("cp.async.commit_group;" ::: "memory");
}
__device__ __forceinline__ void cp_wait1() {
    asm volatile("cp.async.wait_group 1;" ::: "memory");
}

__device__ __forceinline__ void ldsm4(uint32_t& r0, uint32_t& r1, uint32_t& r2, uint32_t& r3,
                                      uint32_t addr) {
    asm volatile("ldmatrix.sync.aligned.m8n8.x4.shared.b16 {%0,%1,%2,%3}, [%4];"
                 : "=r"(r0), "=r"(r1), "=r"(r2), "=r"(r3) : "r"(addr));
}

__device__ __forceinline__ void mma16816(float* d, const uint32_t* a, const uint32_t* b) {
    asm volatile(
        "mma.sync.aligned.m16n8k16.row.col.f32.f16.f16.f32 "
        "{%0,%1,%2,%3}, {%4,%5,%6,%7}, {%8,%9}, {%0,%1,%2,%3};"
        : "+f"(d[0]), "+f"(d[1]), "+f"(d[2]), "+f"(d[3])
        : "r"(a[0]), "r"(a[1]), "r"(a[2]), "r"(a[3]), "r"(b[0]), "r"(b[1]));
}

__device__ __forceinline__ float fast_tanh(float x) {
    float e = __expf(2.0f * x);
    return 1.0f - 2.0f / (e + 1.0f);
}

// ---------------- K1: dec_proj = dec_z @ W_dec + b_enc ----------------
__global__ void k_dec(const float* __restrict__ dec_z,
                      const float* __restrict__ W_dec,
                      const float* __restrict__ b_enc) {
    int b = blockIdx.x;
    __shared__ float z[512];
    for (int i = threadIdx.x; i < 512; i += 256) z[i] = dec_z[b * 512 + i];
    __syncthreads();
    for (int a = threadIdx.x; a < An; a += 256) {
        float acc = b_enc[a];
#pragma unroll 8
        for (int k = 0; k < 512; k++)
            acc = fmaf(z[k], W_dec[(size_t)k * An + a], acc);
        g_decproj[b * An + a] = acc;
    }
}

// ---------------- K2: location conv ----------------
__global__ void k_conv(const float* __restrict__ att_prev,
                       const float* __restrict__ conv_w) {
    int b = blockIdx.y;
    int t0 = blockIdx.x * 128;
    int tid = threadIdx.x;
    __shared__ float cw[Cn * KW];
    __shared__ float xs[128 + 200];
    for (int i = tid; i < Cn * KW; i += 128) cw[i] = conv_w[i];
    for (int i = tid; i < 128 + 200; i += 128) {
        int tt = t0 - 100 + i;
        xs[i] = (tt >= 0 && tt < Tn) ? att_prev[b * Tn + tt] : 0.0f;
    }
    __syncthreads();
    int t = t0 + tid;
    if (t < Tn) {
#pragma unroll
        for (int c = 0; c < Cn; c++) {
            float acc = 0.0f;
#pragma unroll 8
            for (int h = 0; h < KW; h++)
                acc = fmaf(cw[c * KW + h], xs[tid + h], acc);
            g_attc[((size_t)b * Tn + t) * Cn + c] = acc;
        }
    }
}

// ---------------- prep A: enc fp32 -> hi/lo fp16 ----------------
__global__ void k_prep_a(const float* __restrict__ enc) {
    size_t i = ((size_t)blockIdx.x * 256 + threadIdx.x) * 4;
    float4 v = *(const float4*)(enc + i);
    __half hx = __float2half_rn(v.x), hy = __float2half_rn(v.y);
    __half hz = __float2half_rn(v.z), hw = __float2half_rn(v.w);
    __half lx = __float2half_rn(v.x - __half2float(hx));
    __half ly = __float2half_rn(v.y - __half2float(hy));
    __half lz = __float2half_rn(v.z - __half2float(hz));
    __half lw = __float2half_rn(v.w - __half2float(hw));
    *(__half2*)(g_ahi + i) = __halves2half2(hx, hy);
    *(__half2*)(g_ahi + i + 2) = __halves2half2(hz, hw);
    *(__half2*)(g_alo + i) = __halves2half2(lx, ly);
    *(__half2*)(g_alo + i + 2) = __halves2half2(lz, lw);
}

// ---------------- prep B: W_enc^T -> hi/lo fp16 [n][k] ----------------
__global__ void k_prep_b(const float* __restrict__ W_enc) {
    __shared__ float tile[32][33];
    int n0 = blockIdx.x * 32, k0 = blockIdx.y * 32;
    int tx = threadIdx.x, ty = threadIdx.y;  // 32 x 8
    for (int i = ty; i < 32; i += 8)
        tile[i][tx] = W_enc[(size_t)(k0 + i) * An + n0 + tx];  // tile[k][n]
    __syncthreads();
    for (int i = ty; i < 32; i += 8) {
        float v = tile[tx][i];  // W_enc[k0+tx][n0+i]
        __half hi = __float2half_rn(v);
        __half lo = __float2half_rn(v - __half2float(hi));
        g_bhi[(size_t)(n0 + i) * En + k0 + tx] = hi;
        g_blo[(size_t)(n0 + i) * En + k0 + tx] = lo;
    }
}

// ---------------- K3: HMMA fp16-split GEMM + fused epilogue ----------------
__global__ __launch_bounds__(256, 1) void k_gemm_e(
    const float* __restrict__ W_att,
    const float* __restrict__ gvec) {
    extern __shared__ char smem[];
    uint32_t sbase = smem_u32(smem);

    int tid = threadIdx.x;
    int wid = tid >> 5, lane = tid & 31;
    int wm = wid >> 2, wn = wid & 3;
    int ntile = blockIdx.x;           // 0..3
    int mtile = blockIdx.y;           // 0..374
    int row0 = mtile * MT;
    int n0 = ntile * NTC;

    float d[4][4][4];
#pragma unroll
    for (int mt = 0; mt < 4; mt++)
#pragma unroll
        for (int nt = 0; nt < 4; nt++)
#pragma unroll
            for (int r = 0; r < 4; r++) d[mt][nt][r] = 0.0f;

    // cp.async issue: 2048 16B-chunks per K-chunk; 8 per thread
    // id: tile = id>>9 (0=Ah,1=Al,2=Bh,3=Bl), row=(id>>2)&127, c=id&3
    auto issue = [&](int ck, int stage) {
        uint32_t sdst = sbase + stage * STAGE_BYTES;
#pragma unroll
        for (int i = 0; i < 8; i++) {
            int id = tid + i * 256;
            int tile = id >> 9;
            int r = (id >> 2) & 127;
            int c = id & 3;
            const __half* src;
            if (tile == 0)      src = g_ahi + (size_t)(row0 + r) * En + ck * BK + c * 8;
            else if (tile == 1) src = g_alo + (size_t)(row0 + r) * En + ck * BK + c * 8;
            else if (tile == 2) src = g_bhi + (size_t)(n0 + r) * En + ck * BK + c * 8;
            else                src = g_blo + (size_t)(n0 + r) * En + ck * BK + c * 8;
            cp_async16(sdst + tile * TILE_BYTES + r * 80 + c * 16, src);
        }
        cp_commit();
    };

    issue(0, 0);
    issue(1, 1);

    // lane-local ldmatrix offsets (bytes)
    uint32_t laneA = (uint32_t)((lane & 15) * 80 + ((lane >> 4) * 8) * 2);
    uint32_t laneB = (uint32_t)((((lane >> 4) << 3) + (lane & 7)) * 80 + (((lane >> 3) & 1) * 8) * 2);
    uint32_t warpA = (uint32_t)(wm * 64 * 80);
    uint32_t warpB = (uint32_t)(wn * 32 * 80);

#pragma unroll 1
    for (int ck = 0; ck < NCHUNK; ck++) {
        cp_wait1();
        __syncthreads();
        if (ck + 2 < NCHUNK) issue(ck + 2, (ck + 2) % NSTAGES);
        else cp_commit();

        uint32_t st = sbase + (ck % NSTAGES) * STAGE_BYTES;
        uint32_t aH_base = st + OFF_AH + warpA + laneA;
        uint32_t aL_base = st + OFF_AL + warpA + laneA;
        uint32_t bH_base = st + OFF_BH + warpB + laneB;
        uint32_t bL_base = st + OFF_BL + warpB + laneB;

#pragma unroll
        for (int kh = 0; kh < 2; kh++) {
            uint32_t ko = kh * 32;  // 16 halves
            uint32_t aH[4][4], aL[4][4], bH[4][2], bL[4][2];
#pragma unroll
            for (int mt = 0; mt < 4; mt++) {
                ldsm4(aH[mt][0], aH[mt][1], aH[mt][2], aH[mt][3],
                      aH_base + mt * (16 * 80) + ko);
                ldsm4(aL[mt][0], aL[mt][1], aL[mt][2], aL[mt][3],
                      aL_base + mt * (16 * 80) + ko);
            }
#pragma unroll
            for (int np = 0; np < 2; np++) {
                ldsm4(bH[np * 2][0], bH[np * 2][1], bH[np * 2 + 1][0], bH[np * 2 + 1][1],
                      bH_base + np * (16 * 80) + ko);
                ldsm4(bL[np * 2][0], bL[np * 2][1], bL[np * 2 + 1][0], bL[np * 2 + 1][1],
                      bL_base + np * (16 * 80) + ko);
            }
#pragma unroll
            for (int mt = 0; mt < 4; mt++)
#pragma unroll
                for (int nt = 0; nt < 4; nt++) {
                    mma16816(d[mt][nt], aH[mt], bH[nt]);
                    mma16816(d[mt][nt], aH[mt], bL[nt]);
                    mma16816(d[mt][nt], aL[mt], bH[nt]);
                }
        }
    }
    __syncthreads();

    // ---- epilogue (reuse smem) ----
    float* s_dec0 = (float*)smem;          // 128
    float* s_dec1 = s_dec0 + 128;          // 128
    float* s_gv   = s_dec1 + 128;          // 128
    float* s_wat  = s_gv + 128;            // [10][128]
    float* s_atc  = s_wat + Cn * 128;      // [128][10]
    float* s_e    = s_atc + 128 * Cn;      // [128][4]

    int b0 = row0 / Tn;
    int b1 = (row0 + MT - 1) / Tn;
    if (tid < 128) {
        s_dec0[tid] = g_decproj[b0 * An + n0 + tid];
        s_dec1[tid] = g_decproj[b1 * An + n0 + tid];
        s_gv[tid] = gvec[n0 + tid];
    }
    for (int i = tid; i < Cn * 128; i += 256)
        s_wat[i] = W_att[(i >> 7) * An + n0 + (i & 127)];
    for (int i = tid; i < 128 * Cn; i += 256) {
        int r = i / Cn, c = i % Cn;
        int grow = row0 + r;
        int b = grow / Tn, t = grow - b * Tn;
        s_atc[r * Cn + c] = g_attc[((size_t)b * Tn + t) * Cn + c];
    }
    __syncthreads();

    int gid = lane >> 2, tid2 = lane & 3;
#pragma unroll
    for (int mt = 0; mt < 4; mt++) {
        int r0l = wm * 64 + mt * 16 + gid;
        int r1l = r0l + 8;
        int gb0 = (row0 + r0l) / Tn;
        int gb1 = (row0 + r1l) / Tn;
        const float* dec0 = (gb0 == b0) ? s_dec0 : s_dec1;
        const float* dec1 = (gb1 == b0) ? s_dec0 : s_dec1;
        float s0 = 0.0f, s1 = 0.0f;
#pragma unroll
        for (int nt = 0; nt < 4; nt++) {
            int n = wn * 32 + nt * 8 + tid2 * 2;
#pragma unroll
            for (int j = 0; j < 2; j++) {
                int nn = n + j;
                float v0 = d[mt][nt][j] + dec0[nn];
                float v1 = d[mt][nt][2 + j] + dec1[nn];
#pragma unroll
                for (int c = 0; c < Cn; c++) {
                    float w = s_wat[c * 128 + nn];
                    v0 = fmaf(s_atc[r0l * Cn + c], w, v0);
                    v1 = fmaf(s_atc[r1l * Cn + c], w, v1);
                }
                s0 = fmaf(fast_tanh(v0), s_gv[nn], s0);
                s1 = fmaf(fast_tanh(v1), s_gv[nn], s1);
            }
        }
        s0 += __shfl_xor_sync(0xffffffffu, s0, 1);
        s0 += __shfl_xor_sync(0xffffffffu, s0, 2);
        s1 += __shfl_xor_sync(0xffffffffu, s1, 1);
        s1 += __shfl_xor_sync(0xffffffffu, s1, 2);
        if (tid2 == 0) {
            s_e[r0l * 4 + wn] = s0;
            s_e[r1l * 4 + wn] = s1;
        }
    }
    __syncthreads();
    if (tid < 128) {
        float e = s_e[tid * 4 + 0] + s_e[tid * 4 + 1] + s_e[tid * 4 + 2] + s_e[tid * 4 + 3];
        int grow = row0 + tid;
        int b = grow / Tn, t = grow - b * Tn;
        g_epart[((size_t)b * Tn + t) * NA_CHUNKS + ntile] = e;
    }
}

// ---------------- K4: softmax(2*e) -> w ----------------
__global__ void k_softmax(float* __restrict__ w_out) {
    int b = blockIdx.x, tid = threadIdx.x;
    __shared__ float es[Tn];
    __shared__ float red[512];
    for (int t = tid; t < Tn; t += 512) {
        const float* p = &g_epart[((size_t)b * Tn + t) * NA_CHUNKS];
        es[t] = 2.0f * (p[0] + p[1] + p[2] + p[3]);
    }
    __syncthreads();
    float mx = -1e30f;
    for (int t = tid; t < Tn; t += 512) mx = fmaxf(mx, es[t]);
    red[tid] = mx;
    __syncthreads();
    for (int s = 256; s > 0; s >>= 1) {
        if (tid < s) red[tid] = fmaxf(red[tid], red[tid + s]);
        __syncthreads();
    }
    mx = red[0];
    __syncthreads();
    float sum = 0.0f;
    for (int t = tid; t < Tn; t += 512) {
        float ex = __expf(es[t] - mx);
        es[t] = ex;
        sum += ex;
    }
    red[tid] = sum;
    __syncthreads();
    for (int s = 256; s > 0; s >>= 1) {
        if (tid < s) red[tid] += red[tid + s];
        __syncthreads();
    }
    float inv = 1.0f / red[0];
    for (int t = tid; t < Tn; t += 512) w_out[b * Tn + t] = es[t] * inv;
}

// ---------------- K5: context partials ----------------
__global__ void k_ctx(const float* __restrict__ enc,
                      const float* __restrict__ w) {
    int b = blockIdx.y, tc = blockIdx.x, e = threadIdx.x;
    const float* encb = enc + (size_t)b * Tn * En;
    const float* wb = w + b * Tn;
    int t0 = tc * 100;
    float acc = 0.0f;
#pragma unroll 5
    for (int t = t0; t < t0 + 100; t++)
        acc = fmaf(wb[t], encb[(size_t)t * En + e], acc);
    g_cpart[((size_t)b * TC_CHUNKS + tc) * En + e] = acc;
}

// ---------------- K6: out_c = c @ W_o + b_o ----------------
__global__ void k_out(const float* __restrict__ W_o,
                      const float* __restrict__ b_o,
                      float* __restrict__ out_c) {
    int b = blockIdx.y;
    int o = blockIdx.x * 128 + threadIdx.x;
    __shared__ float cs[En];
    for (int e = threadIdx.x; e < En; e += 128) {
        float s = 0.0f;
#pragma unroll
        for (int ch = 0; ch < TC_CHUNKS; ch++)
            s += g_cpart[((size_t)b * TC_CHUNKS + ch) * En + e];
        cs[e] = s;
    }
    __syncthreads();
    float acc = b_o[o];
#pragma unroll 8
    for (int e = 0; e < En; e++)
        acc = fmaf(cs[e], W_o[(size_t)e * On + o], acc);
    out_c[(size_t)b * On + o] = acc;
}

// ---------------- launch ----------------
extern "C" void kernel_launch(void* const* d_in, const int* in_sizes, int n_in,
                              void* d_out, int out_size) {
    const float* enc      = (const float*)d_in[0];
    const float* dec_z    = (const float*)d_in[2];
    const float* att_prev = (const float*)d_in[3];
    const float* W_enc    = (const float*)d_in[4];
    const float* b_enc    = (const float*)d_in[5];
    const float* W_dec    = (const float*)d_in[6];
    const float* W_att    = (const float*)d_in[7];
    const float* conv_w   = (const float*)d_in[8];
    const float* gvec     = (const float*)d_in[9];
    const float* W_o      = (const float*)d_in[10];
    const float* b_o      = (const float*)d_in[11];

    float* out   = (float*)d_out;
    float* out_c = out;            // [B, O]
    float* out_w = out + Bn * On;  // [B, T]

    cudaFuncSetAttribute(k_gemm_e, cudaFuncAttributeMaxDynamicSharedMemorySize, SMEM_GEMM);

    k_prep_a<<<24000, 256>>>(enc);
    k_prep_b<<<dim3(16, 16), dim3(32, 8)>>>(W_enc);
    k_dec<<<Bn, 256>>>(dec_z, W_dec, b_enc);
    k_conv<<<dim3((Tn + 127) / 128, Bn), 128>>>(att_prev, conv_w);
    k_gemm_e<<<dim3(NTILES, MTILES), 256, SMEM_GEMM>>>(W_att, gvec);
    k_softmax<<<Bn, 512>>>(out_w);
    k_ctx<<<dim3(TC_CHUNKS, Bn), 512>>>(enc, out_w);
    k_out<<<dim3(On / 128, Bn), 128>>>(W_o, b_o, out_c);
}

// round 4
// speedup vs baseline: 1.9940x; 1.1278x over previous
#include <cuda_runtime.h>
#include <cuda_fp16.h>
#include <cstdint>

#define Bn 32
#define Tn 1500
#define En 512
#define An 512
#define Cn 10
#define KW 201
#define On 512
#define NA_CHUNKS 8
#define TC_CHUNKS 15

#define MT 128
#define NTC 64             // CTA n-tile
#define BK 32
#define NCHUNK 16          // 512/32
#define MTILES 375
#define NTILES 8

#define OFF_AL 10240
#define OFF_BH 20480
#define OFF_BL 25600
#define STAGE_BYTES 30720
#define NSTAGES 3
#define SMEM_GEMM (NSTAGES * STAGE_BYTES)

// ---------------- scratch ----------------
__device__ float g_decproj[Bn * An];
__device__ float g_attc[Bn * Tn * Cn];
__device__ float g_epart[Bn * Tn * NA_CHUNKS];
__device__ float g_cpart[Bn * TC_CHUNKS * En];
__device__ __half g_ahi[(size_t)Bn * Tn * En];
__device__ __half g_alo[(size_t)Bn * Tn * En];
__device__ __half g_bhi[An * En];   // [n][k]
__device__ __half g_blo[An * En];

// ---------------- helpers ----------------
__device__ __forceinline__ uint32_t smem_u32(const void* p) {
    uint32_t a;
    asm("{ .reg .u64 t; cvta.to.shared.u64 t, %1; cvt.u32.u64 %0, t; }" : "=r"(a) : "l"(p));
    return a;
}

__device__ __forceinline__ void cp_async16(uint32_t dst, const void* src) {
    asm volatile("cp.async.cg.shared.global [%0], [%1], 16;" :: "r"(dst), "l"(src));
}
__device__ __forceinline__ void cp_commit() {
    asm volatile("cp.async.commit_group;" ::: "memory");
}
__device__ __forceinline__ void cp_wait1() {
    asm volatile("cp.async.wait_group 1;" ::: "memory");
}

__device__ __forceinline__ void ldsm4(uint32_t& r0, uint32_t& r1, uint32_t& r2, uint32_t& r3,
                                      uint32_t addr) {
    asm volatile("ldmatrix.sync.aligned.m8n8.x4.shared.b16 {%0,%1,%2,%3}, [%4];"
                 : "=r"(r0), "=r"(r1), "=r"(r2), "=r"(r3) : "r"(addr));
}

__device__ __forceinline__ void mma16816(float* d, const uint32_t* a, const uint32_t* b) {
    asm volatile(
        "mma.sync.aligned.m16n8k16.row.col.f32.f16.f16.f32 "
        "{%0,%1,%2,%3}, {%4,%5,%6,%7}, {%8,%9}, {%0,%1,%2,%3};"
        : "+f"(d[0]), "+f"(d[1]), "+f"(d[2]), "+f"(d[3])
        : "r"(a[0]), "r"(a[1]), "r"(a[2]), "r"(a[3]), "r"(b[0]), "r"(b[1]));
}

__device__ __forceinline__ float fast_tanh(float x) {
    float e = __expf(2.0f * x);
    return 1.0f - 2.0f / (e + 1.0f);
}

// ---------------- K1: dec_proj = dec_z @ W_dec + b_enc ----------------
__global__ void k_dec(const float* __restrict__ dec_z,
                      const float* __restrict__ W_dec,
                      const float* __restrict__ b_enc) {
    int b = blockIdx.y;
    int a = blockIdx.x * 128 + threadIdx.x;
    __shared__ float z[512];
    for (int i = threadIdx.x; i < 512; i += 128) z[i] = dec_z[b * 512 + i];
    __syncthreads();
    float acc = b_enc[a];
#pragma unroll 8
    for (int k = 0; k < 512; k++)
        acc = fmaf(z[k], W_dec[(size_t)k * An + a], acc);
    g_decproj[b * An + a] = acc;
}

// ---------------- K2: location conv (thread per (t,c)) ----------------
__global__ void k_conv(const float* __restrict__ att_prev,
                       const float* __restrict__ conv_w) {
    int b = blockIdx.y;
    int t0 = blockIdx.x * 64;
    int tid = threadIdx.x;          // 640 threads
    int toff = tid & 63;
    int c = tid >> 6;               // 0..9
    __shared__ float cw[Cn * KW];
    __shared__ float xs[64 + 200];
    for (int i = tid; i < Cn * KW; i += 640) cw[i] = conv_w[i];
    for (int i = tid; i < 64 + 200; i += 640) {
        int tt = t0 - 100 + i;
        xs[i] = (tt >= 0 && tt < Tn) ? att_prev[b * Tn + tt] : 0.0f;
    }
    __syncthreads();
    int t = t0 + toff;
    if (t < Tn) {
        const float* cwc = cw + c * KW;
        float acc = 0.0f;
#pragma unroll 8
        for (int h = 0; h < KW; h++)
            acc = fmaf(cwc[h], xs[toff + h], acc);
        g_attc[((size_t)b * Tn + t) * Cn + c] = acc;
    }
}

// ---------------- prep A: enc fp32 -> hi/lo fp16 ----------------
__global__ void k_prep_a(const float* __restrict__ enc) {
    size_t i = ((size_t)blockIdx.x * 256 + threadIdx.x) * 4;
    float4 v = *(const float4*)(enc + i);
    __half hx = __float2half_rn(v.x), hy = __float2half_rn(v.y);
    __half hz = __float2half_rn(v.z), hw = __float2half_rn(v.w);
    __half lx = __float2half_rn(v.x - __half2float(hx));
    __half ly = __float2half_rn(v.y - __half2float(hy));
    __half lz = __float2half_rn(v.z - __half2float(hz));
    __half lw = __float2half_rn(v.w - __half2float(hw));
    *(__half2*)(g_ahi + i) = __halves2half2(hx, hy);
    *(__half2*)(g_ahi + i + 2) = __halves2half2(hz, hw);
    *(__half2*)(g_alo + i) = __halves2half2(lx, ly);
    *(__half2*)(g_alo + i + 2) = __halves2half2(lz, lw);
}

// ---------------- prep B: W_enc^T -> hi/lo fp16 [n][k] ----------------
__global__ void k_prep_b(const float* __restrict__ W_enc) {
    __shared__ float tile[32][33];
    int n0 = blockIdx.x * 32, k0 = blockIdx.y * 32;
    int tx = threadIdx.x, ty = threadIdx.y;  // 32 x 8
    for (int i = ty; i < 32; i += 8)
        tile[i][tx] = W_enc[(size_t)(k0 + i) * An + n0 + tx];
    __syncthreads();
    for (int i = ty; i < 32; i += 8) {
        float v = tile[tx][i];
        __half hi = __float2half_rn(v);
        __half lo = __float2half_rn(v - __half2float(hi));
        g_bhi[(size_t)(n0 + i) * En + k0 + tx] = hi;
        g_blo[(size_t)(n0 + i) * En + k0 + tx] = lo;
    }
}

// ---------------- K3: HMMA fp16-split GEMM + fused epilogue ----------------
// CTA 128x64, 8 warps (4m x 2n), warp 32x32, 3-stage cp.async, 2 CTAs/SM.
__global__ __launch_bounds__(256, 2) void k_gemm_e(
    const float* __restrict__ W_att,
    const float* __restrict__ gvec) {
    extern __shared__ char smem[];
    uint32_t sbase = smem_u32(smem);

    int tid = threadIdx.x;
    int wid = tid >> 5, lane = tid & 31;
    int wm = wid >> 1, wn = wid & 1;         // 4m x 2n
    int ntile = blockIdx.x;                  // 0..7
    int mtile = blockIdx.y;                  // 0..374
    int row0 = mtile * MT;
    int n0 = ntile * NTC;

    float d[2][4][4];
#pragma unroll
    for (int mt = 0; mt < 2; mt++)
#pragma unroll
        for (int nt = 0; nt < 4; nt++)
#pragma unroll
            for (int r = 0; r < 4; r++) d[mt][nt][r] = 0.0f;

    int lr = tid >> 2, lc = tid & 3;         // lr 0..63, lc 0..3
    const __half* pah = g_ahi + (size_t)(row0 + lr) * En + lc * 8;
    const __half* pal = g_alo + (size_t)(row0 + lr) * En + lc * 8;
    const __half* pbh = g_bhi + (size_t)(n0 + lr) * En + lc * 8;
    const __half* pbl = g_blo + (size_t)(n0 + lr) * En + lc * 8;
    uint32_t da0 = (uint32_t)(lr * 80 + lc * 16);
    uint32_t da1 = (uint32_t)((64 + lr) * 80 + lc * 16);

    auto issue = [&](int ck, int stage) {
        uint32_t s = sbase + stage * STAGE_BYTES;
        size_t ko = (size_t)ck * BK;
        cp_async16(s + da0, pah + ko);
        cp_async16(s + da1, pah + 64 * En + ko);
        cp_async16(s + OFF_AL + da0, pal + ko);
        cp_async16(s + OFF_AL + da1, pal + 64 * En + ko);
        cp_async16(s + OFF_BH + da0, pbh + ko);
        cp_async16(s + OFF_BL + da0, pbl + ko);
        cp_commit();
    };

    issue(0, 0);
    issue(1, 1);

    uint32_t laneA = (uint32_t)((lane & 15) * 80 + (lane >> 4) * 16);
    uint32_t laneB = (uint32_t)(((((lane >> 4) << 3) + (lane & 7))) * 80 + ((lane >> 3) & 1) * 16);
    uint32_t warpA = (uint32_t)(wm * 32 * 80);
    uint32_t warpB = (uint32_t)(wn * 32 * 80);

#pragma unroll 1
    for (int ck = 0; ck < NCHUNK; ck++) {
        cp_wait1();
        __syncthreads();
        if (ck + 2 < NCHUNK) issue(ck + 2, (ck + 2) % NSTAGES);
        else cp_commit();

        uint32_t st = sbase + (ck % NSTAGES) * STAGE_BYTES;
        uint32_t aH_base = st + warpA + laneA;
        uint32_t aL_base = st + OFF_AL + warpA + laneA;
        uint32_t bH_base = st + OFF_BH + warpB + laneB;
        uint32_t bL_base = st + OFF_BL + warpB + laneB;

#pragma unroll
        for (int kh = 0; kh < 2; kh++) {
            uint32_t ko = kh * 32;  // 16 halves
            uint32_t aH[2][4], aL[2][4], bH[4][2], bL[4][2];
#pragma unroll
            for (int mt = 0; mt < 2; mt++) {
                ldsm4(aH[mt][0], aH[mt][1], aH[mt][2], aH[mt][3],
                      aH_base + mt * (16 * 80) + ko);
                ldsm4(aL[mt][0], aL[mt][1], aL[mt][2], aL[mt][3],
                      aL_base + mt * (16 * 80) + ko);
            }
#pragma unroll
            for (int np = 0; np < 2; np++) {
                ldsm4(bH[np * 2][0], bH[np * 2][1], bH[np * 2 + 1][0], bH[np * 2 + 1][1],
                      bH_base + np * (16 * 80) + ko);
                ldsm4(bL[np * 2][0], bL[np * 2][1], bL[np * 2 + 1][0], bL[np * 2 + 1][1],
                      bL_base + np * (16 * 80) + ko);
            }
#pragma unroll
            for (int mt = 0; mt < 2; mt++)
#pragma unroll
                for (int nt = 0; nt < 4; nt++) {
                    mma16816(d[mt][nt], aH[mt], bH[nt]);
                    mma16816(d[mt][nt], aH[mt], bL[nt]);
                    mma16816(d[mt][nt], aL[mt], bH[nt]);
                }
        }
    }
    __syncthreads();

    // ---- epilogue (reuse smem) ----
    float* s_dec0 = (float*)smem;          // 64
    float* s_dec1 = s_dec0 + 64;           // 64
    float* s_gv   = s_dec1 + 64;           // 64
    float* s_wat  = s_gv + 64;             // [10][64]
    float* s_atc  = s_wat + Cn * 64;       // [128][10]
    float* s_e    = s_atc + 128 * Cn;      // [128][2]

    int b0 = row0 / Tn;
    int b1 = (row0 + MT - 1) / Tn;
    if (tid < 64) {
        s_dec0[tid] = g_decproj[b0 * An + n0 + tid];
        s_dec1[tid] = g_decproj[b1 * An + n0 + tid];
        s_gv[tid] = gvec[n0 + tid];
    }
    for (int i = tid; i < Cn * 64; i += 256)
        s_wat[i] = W_att[(i >> 6) * An + n0 + (i & 63)];
    for (int i = tid; i < 128 * Cn; i += 256) {
        int r = i / Cn, c = i % Cn;
        int grow = row0 + r;
        int b = grow / Tn, t = grow - b * Tn;
        s_atc[r * Cn + c] = g_attc[((size_t)b * Tn + t) * Cn + c];
    }
    __syncthreads();

    int gid = lane >> 2, tid2 = lane & 3;
#pragma unroll
    for (int mt = 0; mt < 2; mt++) {
        int r0l = wm * 32 + mt * 16 + gid;
        int r1l = r0l + 8;
        int gb0 = (row0 + r0l) / Tn;
        int gb1 = (row0 + r1l) / Tn;
        const float* dec0 = (gb0 == b0) ? s_dec0 : s_dec1;
        const float* dec1 = (gb1 == b0) ? s_dec0 : s_dec1;
        float s0 = 0.0f, s1 = 0.0f;
#pragma unroll
        for (int nt = 0; nt < 4; nt++) {
            int n = wn * 32 + nt * 8 + tid2 * 2;
#pragma unroll
            for (int j = 0; j < 2; j++) {
                int nn = n + j;
                float v0 = d[mt][nt][j] + dec0[nn];
                float v1 = d[mt][nt][2 + j] + dec1[nn];
#pragma unroll
                for (int c = 0; c < Cn; c++) {
                    float w = s_wat[c * 64 + nn];
                    v0 = fmaf(s_atc[r0l * Cn + c], w, v0);
                    v1 = fmaf(s_atc[r1l * Cn + c], w, v1);
                }
                s0 = fmaf(fast_tanh(v0), s_gv[nn], s0);
                s1 = fmaf(fast_tanh(v1), s_gv[nn], s1);
            }
        }
        s0 += __shfl_xor_sync(0xffffffffu, s0, 1);
        s0 += __shfl_xor_sync(0xffffffffu, s0, 2);
        s1 += __shfl_xor_sync(0xffffffffu, s1, 1);
        s1 += __shfl_xor_sync(0xffffffffu, s1, 2);
        if (tid2 == 0) {
            s_e[r0l * 2 + wn] = s0;
            s_e[r1l * 2 + wn] = s1;
        }
    }
    __syncthreads();
    if (tid < 128) {
        float e = s_e[tid * 2 + 0] + s_e[tid * 2 + 1];
        int grow = row0 + tid;
        int b = grow / Tn, t = grow - b * Tn;
        g_epart[((size_t)b * Tn + t) * NA_CHUNKS + ntile] = e;
    }
}

// ---------------- K4: softmax(2*e) -> w ----------------
__global__ void k_softmax(float* __restrict__ w_out) {
    int b = blockIdx.x, tid = threadIdx.x;
    __shared__ float es[Tn];
    __shared__ float red[512];
    for (int t = tid; t < Tn; t += 512) {
        const float* p = &g_epart[((size_t)b * Tn + t) * NA_CHUNKS];
        float s = 0.0f;
#pragma unroll
        for (int i = 0; i < NA_CHUNKS; i++) s += p[i];
        es[t] = 2.0f * s;
    }
    __syncthreads();
    float mx = -1e30f;
    for (int t = tid; t < Tn; t += 512) mx = fmaxf(mx, es[t]);
    red[tid] = mx;
    __syncthreads();
    for (int s = 256; s > 0; s >>= 1) {
        if (tid < s) red[tid] = fmaxf(red[tid], red[tid + s]);
        __syncthreads();
    }
    mx = red[0];
    __syncthreads();
    float sum = 0.0f;
    for (int t = tid; t < Tn; t += 512) {
        float ex = __expf(es[t] - mx);
        es[t] = ex;
        sum += ex;
    }
    red[tid] = sum;
    __syncthreads();
    for (int s = 256; s > 0; s >>= 1) {
        if (tid < s) red[tid] += red[tid + s];
        __syncthreads();
    }
    float inv = 1.0f / red[0];
    for (int t = tid; t < Tn; t += 512) w_out[b * Tn + t] = es[t] * inv;
}

// ---------------- K5: context partials ----------------
__global__ void k_ctx(const float* __restrict__ enc,
                      const float* __restrict__ w) {
    int b = blockIdx.y, tc = blockIdx.x, e = threadIdx.x;
    const float* encb = enc + (size_t)b * Tn * En;
    const float* wb = w + b * Tn;
    int t0 = tc * 100;
    float acc = 0.0f;
#pragma unroll 5
    for (int t = t0; t < t0 + 100; t++)
        acc = fmaf(wb[t], encb[(size_t)t * En + e], acc);
    g_cpart[((size_t)b * TC_CHUNKS + tc) * En + e] = acc;
}

// ---------------- K6: out_c = c @ W_o + b_o ----------------
__global__ void k_out(const float* __restrict__ W_o,
                      const float* __restrict__ b_o,
                      float* __restrict__ out_c) {
    int b = blockIdx.y;
    int o = blockIdx.x * 128 + threadIdx.x;
    __shared__ float cs[En];
    for (int e = threadIdx.x; e < En; e += 128) {
        float s = 0.0f;
#pragma unroll
        for (int ch = 0; ch < TC_CHUNKS; ch++)
            s += g_cpart[((size_t)b * TC_CHUNKS + ch) * En + e];
        cs[e] = s;
    }
    __syncthreads();
    float acc = b_o[o];
#pragma unroll 8
    for (int e = 0; e < En; e++)
        acc = fmaf(cs[e], W_o[(size_t)e * On + o], acc);
    out_c[(size_t)b * On + o] = acc;
}

// ---------------- launch ----------------
extern "C" void kernel_launch(void* const* d_in, const int* in_sizes, int n_in,
                              void* d_out, int out_size) {
    const float* enc      = (const float*)d_in[0];
    const float* dec_z    = (const float*)d_in[2];
    const float* att_prev = (const float*)d_in[3];
    const float* W_enc    = (const float*)d_in[4];
    const float* b_enc    = (const float*)d_in[5];
    const float* W_dec    = (const float*)d_in[6];
    const float* W_att    = (const float*)d_in[7];
    const float* conv_w   = (const float*)d_in[8];
    const float* gvec     = (const float*)d_in[9];
    const float* W_o      = (const float*)d_in[10];
    const float* b_o      = (const float*)d_in[11];

    float* out   = (float*)d_out;
    float* out_c = out;            // [B, O]
    float* out_w = out + Bn * On;  // [B, T]

    cudaFuncSetAttribute(k_gemm_e, cudaFuncAttributeMaxDynamicSharedMemorySize, SMEM_GEMM);

    k_prep_a<<<24000, 256>>>(enc);
    k_prep_b<<<dim3(16, 16), dim3(32, 8)>>>(W_enc);
    k_dec<<<dim3(4, Bn), 128>>>(dec_z, W_dec, b_enc);
    k_conv<<<dim3((Tn + 63) / 64, Bn), 640>>>(att_prev, conv_w);
    k_gemm_e<<<dim3(NTILES, MTILES), 256, SMEM_GEMM>>>(W_att, gvec);
    k_softmax<<<Bn, 512>>>(out_w);
    k_ctx<<<dim3(TC_CHUNKS, Bn), 512>>>(enc, out_w);
    k_out<<<dim3(On / 128, Bn), 128>>>(W_o, b_o, out_c);
}

// round 6
// speedup vs baseline: 2.1240x; 1.0652x over previous
#include <cuda_runtime.h>
#include <cuda_fp16.h>
#include <cstdint>

#define Bn 32
#define Tn 1500
#define En 512
#define An 512
#define Cn 10
#define KW 201
#define On 512
#define NA_CHUNKS 8
#define TC_CHUNKS 15

#define MT 128
#define NTC 64
#define BK 32
#define NCHUNK 16
#define MTILES 375
#define NTILES 8

#define OFF_AL 10240
#define OFF_BH 20480
#define OFF_BL 25600
#define STAGE_BYTES 30720
#define SMEM_GEMM STAGE_BYTES

// ---------------- scratch ----------------
__device__ float g_decproj[Bn * An];
__device__ float g_attc[Bn * Tn * Cn];
__device__ float g_epart[Bn * Tn * NA_CHUNKS];
__device__ float g_cpart[Bn * TC_CHUNKS * En];
__device__ __half g_bhi[An * En];   // [n][k]
__device__ __half g_blo[An * En];

// ---------------- helpers ----------------
__device__ __forceinline__ uint32_t smem_u32(const void* p) {
    uint32_t a;
    asm("{ .reg .u64 t; cvta.to.shared.u64 t, %1; cvt.u32.u64 %0, t; }" : "=r"(a) : "l"(p));
    return a;
}

__device__ __forceinline__ void ldsm4(uint32_t& r0, uint32_t& r1, uint32_t& r2, uint32_t& r3,
                                      uint32_t addr) {
    asm volatile("ldmatrix.sync.aligned.m8n8.x4.shared.b16 {%0,%1,%2,%3}, [%4];"
                 : "=r"(r0), "=r"(r1), "=r"(r2), "=r"(r3) : "r"(addr));
}

__device__ __forceinline__ void mma16816(float* d, const uint32_t* a, const uint32_t* b) {
    asm volatile(
        "mma.sync.aligned.m16n8k16.row.col.f32.f16.f16.f32 "
        "{%0,%1,%2,%3}, {%4,%5,%6,%7}, {%8,%9}, {%0,%1,%2,%3};"
        : "+f"(d[0]), "+f"(d[1]), "+f"(d[2]), "+f"(d[3])
        : "r"(a[0]), "r"(a[1]), "r"(a[2]), "r"(a[3]), "r"(b[0]), "r"(b[1]));
}

__device__ __forceinline__ float fast_tanh(float x) {
    float e = __expf(2.0f * x);
    return 1.0f - 2.0f / (e + 1.0f);
}

__device__ __forceinline__ uint32_t h2u(__half2 h) {
    uint32_t u;
    asm("mov.b32 %0, %1;" : "=r"(u) : "r"(*reinterpret_cast<uint32_t*>(&h)));
    return *reinterpret_cast<uint32_t*>(&h);
}

struct H8 { uint32_t u[4]; };

// split 8 fp32 into hi fp16x8 and lo fp16x8
__device__ __forceinline__ void split8(const float4& A, const float4& B, H8& hi, H8& lo) {
    __half2 h0 = __floats2half2_rn(A.x, A.y);
    __half2 h1 = __floats2half2_rn(A.z, A.w);
    __half2 h2 = __floats2half2_rn(B.x, B.y);
    __half2 h3 = __floats2half2_rn(B.z, B.w);
    float2 f0 = __half22float2(h0), f1 = __half22float2(h1);
    float2 f2 = __half22float2(h2), f3 = __half22float2(h3);
    __half2 l0 = __floats2half2_rn(A.x - f0.x, A.y - f0.y);
    __half2 l1 = __floats2half2_rn(A.z - f1.x, A.w - f1.y);
    __half2 l2 = __floats2half2_rn(B.x - f2.x, B.y - f2.y);
    __half2 l3 = __floats2half2_rn(B.z - f3.x, B.w - f3.y);
    hi.u[0] = h2u(h0); hi.u[1] = h2u(h1);
    hi.u[2] = h2u(h2); hi.u[3] = h2u(h3);
    lo.u[0] = h2u(l0); lo.u[1] = h2u(l1);
    lo.u[2] = h2u(l2); lo.u[3] = h2u(l3);
}

// ---------------- K1: dec_proj ----------------
__global__ void k_dec(const float* __restrict__ dec_z,
                      const float* __restrict__ W_dec,
                      const float* __restrict__ b_enc) {
    int b = blockIdx.y;
    int a = blockIdx.x * 128 + threadIdx.x;
    __shared__ float z[512];
    for (int i = threadIdx.x; i < 512; i += 128) z[i] = dec_z[b * 512 + i];
    __syncthreads();
    float acc = b_enc[a];
#pragma unroll 8
    for (int k = 0; k < 512; k++)
        acc = fmaf(z[k], W_dec[(size_t)k * An + a], acc);
    g_decproj[b * An + a] = acc;
}

// ---------------- K2: location conv, sliding-window (8 t per thread) ------
__global__ void k_conv(const float* __restrict__ att_prev,
                       const float* __restrict__ conv_w) {
    int b = blockIdx.y;
    int t0 = blockIdx.x * 128;
    int tid = threadIdx.x;           // 160 threads: 16 t-groups x 10 c
    int tg = tid & 15, c = tid >> 4;
    int tb = tg * 8;
    __shared__ float cw[Cn * KW];
    __shared__ float xs[128 + 200];
    __shared__ float so[128 * Cn];
    for (int i = tid; i < Cn * KW; i += 160) cw[i] = conv_w[i];
    for (int i = tid; i < 128 + 200; i += 160) {
        int tt = t0 - 100 + i;
        xs[i] = (tt >= 0 && tt < Tn) ? att_prev[b * Tn + tt] : 0.0f;
    }
    __syncthreads();

    float acc[8] = {0, 0, 0, 0, 0, 0, 0, 0};
    float win[8];
#pragma unroll
    for (int j = 0; j < 8; j++) win[j] = xs[tb + j];
    const float* cwc = cw + c * KW;
#pragma unroll 8
    for (int h = 0; h < KW; h++) {
        float coef = cwc[h];
#pragma unroll
        for (int j = 0; j < 8; j++) acc[j] = fmaf(coef, win[j], acc[j]);
#pragma unroll
        for (int j = 0; j < 7; j++) win[j] = win[j + 1];
        win[7] = xs[tb + h + 8];
    }
#pragma unroll
    for (int j = 0; j < 8; j++) so[(tb + j) * Cn + c] = acc[j];
    __syncthreads();

    // coalesced store of [128][10] block
    int nvalid = Tn - t0;
    if (nvalid > 128) nvalid = 128;
    float* dst = g_attc + ((size_t)b * Tn + t0) * Cn;
    for (int i = tid; i < nvalid * Cn; i += 160) dst[i] = so[i];
}

// ---------------- prep B: W_enc^T -> hi/lo fp16 [n][k] ----------------
__global__ void k_prep_b(const float* __restrict__ W_enc) {
    __shared__ float tile[32][33];
    int n0 = blockIdx.x * 32, k0 = blockIdx.y * 32;
    int tx = threadIdx.x, ty = threadIdx.y;  // 32 x 8
    for (int i = ty; i < 32; i += 8)
        tile[i][tx] = W_enc[(size_t)(k0 + i) * An + n0 + tx];
    __syncthreads();
    for (int i = ty; i < 32; i += 8) {
        float v = tile[tx][i];
        __half hi = __float2half_rn(v);
        __half lo = __float2half_rn(v - __half2float(hi));
        g_bhi[(size_t)(n0 + i) * En + k0 + tx] = hi;
        g_blo[(size_t)(n0 + i) * En + k0 + tx] = lo;
    }
}

// ---------------- K3: HMMA fp16-split GEMM (A fp32 direct) ----------------
// CTA 128x64, 8 warps (4m x 2n), warp 32x32, single-buffer + reg prefetch.
__global__ __launch_bounds__(256, 2) void k_gemm_e(
    const float* __restrict__ enc,
    const float* __restrict__ W_att,
    const float* __restrict__ gvec) {
    extern __shared__ char smem[];
    uint32_t sbase = smem_u32(smem);

    int tid = threadIdx.x;
    int wid = tid >> 5, lane = tid & 31;
    int wm = wid >> 1, wn = wid & 1;
    int ntile = blockIdx.x;
    int mtile = blockIdx.y;
    int row0 = mtile * MT;
    int n0 = ntile * NTC;

    float d[2][4][4];
#pragma unroll
    for (int mt = 0; mt < 2; mt++)
#pragma unroll
        for (int nt = 0; nt < 4; nt++)
#pragma unroll
            for (int r = 0; r < 4; r++) d[mt][nt][r] = 0.0f;

    int lr = tid >> 2, lc = tid & 3;
    const float* pa0 = enc + (size_t)(row0 + lr) * En + lc * 8;
    const float* pa1 = pa0 + (size_t)64 * En;
    const __half* pbh = g_bhi + (size_t)(n0 + lr) * En + lc * 8;
    const __half* pbl = g_blo + (size_t)(n0 + lr) * En + lc * 8;
    uint32_t da0 = (uint32_t)(lr * 80 + lc * 16);
    uint32_t da1 = (uint32_t)((64 + lr) * 80 + lc * 16);

    float4 a0a, a0b, a1a, a1b;
    uint4 rbh, rbl;
    auto load_regs = [&](int ck) {
        int ko = ck * BK;
        a0a = *(const float4*)(pa0 + ko);
        a0b = *(const float4*)(pa0 + ko + 4);
        a1a = *(const float4*)(pa1 + ko);
        a1b = *(const float4*)(pa1 + ko + 4);
        rbh = *(const uint4*)(pbh + ko);
        rbl = *(const uint4*)(pbl + ko);
    };
    load_regs(0);

    uint32_t laneA = (uint32_t)((lane & 15) * 80 + (lane >> 4) * 16);
    uint32_t laneB = (uint32_t)(((((lane >> 4) << 3) + (lane & 7))) * 80 + ((lane >> 3) & 1) * 16);
    uint32_t warpA = (uint32_t)(wm * 32 * 80);
    uint32_t warpB = (uint32_t)(wn * 32 * 80);
    uint32_t aH_base = sbase + warpA + laneA;
    uint32_t aL_base = sbase + OFF_AL + warpA + laneA;
    uint32_t bH_base = sbase + OFF_BH + warpB + laneB;
    uint32_t bL_base = sbase + OFF_BL + warpB + laneB;

#pragma unroll 1
    for (int ck = 0; ck < NCHUNK; ck++) {
        __syncthreads();   // previous MMA done reading smem
        H8 hi, lo;
        split8(a0a, a0b, hi, lo);
        *(uint4*)(smem + da0) = *(uint4*)hi.u;
        *(uint4*)(smem + OFF_AL + da0) = *(uint4*)lo.u;
        split8(a1a, a1b, hi, lo);
        *(uint4*)(smem + da1) = *(uint4*)hi.u;
        *(uint4*)(smem + OFF_AL + da1) = *(uint4*)lo.u;
        *(uint4*)(smem + OFF_BH + da0) = rbh;
        *(uint4*)(smem + OFF_BL + da0) = rbl;
        __syncthreads();
        if (ck + 1 < NCHUNK) load_regs(ck + 1);

#pragma unroll
        for (int kh = 0; kh < 2; kh++) {
            uint32_t ko = kh * 32;  // 16 halves
            uint32_t aH[2][4], aL[2][4], bH[4][2], bL[4][2];
#pragma unroll
            for (int mt = 0; mt < 2; mt++) {
                ldsm4(aH[mt][0], aH[mt][1], aH[mt][2], aH[mt][3],
                      aH_base + mt * (16 * 80) + ko);
                ldsm4(aL[mt][0], aL[mt][1], aL[mt][2], aL[mt][3],
                      aL_base + mt * (16 * 80) + ko);
            }
#pragma unroll
            for (int np = 0; np < 2; np++) {
                ldsm4(bH[np * 2][0], bH[np * 2][1], bH[np * 2 + 1][0], bH[np * 2 + 1][1],
                      bH_base + np * (16 * 80) + ko);
                ldsm4(bL[np * 2][0], bL[np * 2][1], bL[np * 2 + 1][0], bL[np * 2 + 1][1],
                      bL_base + np * (16 * 80) + ko);
            }
#pragma unroll
            for (int mt = 0; mt < 2; mt++)
#pragma unroll
                for (int nt = 0; nt < 4; nt++) {
                    mma16816(d[mt][nt], aH[mt], bH[nt]);
                    mma16816(d[mt][nt], aH[mt], bL[nt]);
                    mma16816(d[mt][nt], aL[mt], bH[nt]);
                }
        }
    }
    __syncthreads();

    // ---- epilogue (reuse smem) ----
    float* s_dec0 = (float*)smem;
    float* s_dec1 = s_dec0 + 64;
    float* s_gv   = s_dec1 + 64;
    float* s_wat  = s_gv + 64;            // [10][64]
    float* s_atc  = s_wat + Cn * 64;      // [128][10]
    float* s_e    = s_atc + 128 * Cn;     // [128][2]

    int b0 = row0 / Tn;
    int b1 = (row0 + MT - 1) / Tn;
    if (tid < 64) {
        s_dec0[tid] = g_decproj[b0 * An + n0 + tid];
        s_dec1[tid] = g_decproj[b1 * An + n0 + tid];
        s_gv[tid] = gvec[n0 + tid];
    }
    for (int i = tid; i < Cn * 64; i += 256)
        s_wat[i] = W_att[(i >> 6) * An + n0 + (i & 63)];
    for (int i = tid; i < 128 * Cn; i += 256) {
        int r = i / Cn, c = i % Cn;
        int grow = row0 + r;
        int b = grow / Tn, t = grow - b * Tn;
        s_atc[r * Cn + c] = g_attc[((size_t)b * Tn + t) * Cn + c];
    }
    __syncthreads();

    int gid = lane >> 2, tid2 = lane & 3;
#pragma unroll
    for (int mt = 0; mt < 2; mt++) {
        int r0l = wm * 32 + mt * 16 + gid;
        int r1l = r0l + 8;
        int gb0 = (row0 + r0l) / Tn;
        int gb1 = (row0 + r1l) / Tn;
        const float* dec0 = (gb0 == b0) ? s_dec0 : s_dec1;
        const float* dec1 = (gb1 == b0) ? s_dec0 : s_dec1;
        float s0 = 0.0f, s1 = 0.0f;
#pragma unroll
        for (int nt = 0; nt < 4; nt++) {
            int n = wn * 32 + nt * 8 + tid2 * 2;
#pragma unroll
            for (int j = 0; j < 2; j++) {
                int nn = n + j;
                float v0 = d[mt][nt][j] + dec0[nn];
                float v1 = d[mt][nt][2 + j] + dec1[nn];
#pragma unroll
                for (int c = 0; c < Cn; c++) {
                    float w = s_wat[c * 64 + nn];
                    v0 = fmaf(s_atc[r0l * Cn + c], w, v0);
                    v1 = fmaf(s_atc[r1l * Cn + c], w, v1);
                }
                s0 = fmaf(fast_tanh(v0), s_gv[nn], s0);
                s1 = fmaf(fast_tanh(v1), s_gv[nn], s1);
            }
        }
        s0 += __shfl_xor_sync(0xffffffffu, s0, 1);
        s0 += __shfl_xor_sync(0xffffffffu, s0, 2);
        s1 += __shfl_xor_sync(0xffffffffu, s1, 1);
        s1 += __shfl_xor_sync(0xffffffffu, s1, 2);
        if (tid2 == 0) {
            s_e[r0l * 2 + wn] = s0;
            s_e[r1l * 2 + wn] = s1;
        }
    }
    __syncthreads();
    if (tid < 128) {
        float e = s_e[tid * 2 + 0] + s_e[tid * 2 + 1];
        int grow = row0 + tid;
        int b = grow / Tn, t = grow - b * Tn;
        g_epart[((size_t)b * Tn + t) * NA_CHUNKS + ntile] = e;
    }
}

// ---------------- K4: softmax ----------------
__global__ void k_softmax(float* __restrict__ w_out) {
    int b = blockIdx.x, tid = threadIdx.x;
    __shared__ float es[Tn];
    __shared__ float red[512];
    for (int t = tid; t < Tn; t += 512) {
        const float* p = &g_epart[((size_t)b * Tn + t) * NA_CHUNKS];
        float s = 0.0f;
#pragma unroll
        for (int i = 0; i < NA_CHUNKS; i++) s += p[i];
        es[t] = 2.0f * s;
    }
    __syncthreads();
    float mx = -1e30f;
    for (int t = tid; t < Tn; t += 512) mx = fmaxf(mx, es[t]);
    red[tid] = mx;
    __syncthreads();
    for (int s = 256; s > 0; s >>= 1) {
        if (tid < s) red[tid] = fmaxf(red[tid], red[tid + s]);
        __syncthreads();
    }
    mx = red[0];
    __syncthreads();
    float sum = 0.0f;
    for (int t = tid; t < Tn; t += 512) {
        float ex = __expf(es[t] - mx);
        es[t] = ex;
        sum += ex;
    }
    red[tid] = sum;
    __syncthreads();
    for (int s = 256; s > 0; s >>= 1) {
        if (tid < s) red[tid] += red[tid + s];
        __syncthreads();
    }
    float inv = 1.0f / red[0];
    for (int t = tid; t < Tn; t += 512) w_out[b * Tn + t] = es[t] * inv;
}

// ---------------- K5: context partials ----------------
__global__ void k_ctx(const float* __restrict__ enc,
                      const float* __restrict__ w) {
    int b = blockIdx.y, tc = blockIdx.x, e = threadIdx.x;
    const float* encb = enc + (size_t)b * Tn * En;
    const float* wb = w + b * Tn;
    int t0 = tc * 100;
    float acc = 0.0f;
#pragma unroll 5
    for (int t = t0; t < t0 + 100; t++)
        acc = fmaf(wb[t], encb[(size_t)t * En + e], acc);
    g_cpart[((size_t)b * TC_CHUNKS + tc) * En + e] = acc;
}

// ---------------- K6: out_c ----------------
__global__ void k_out(const float* __restrict__ W_o,
                      const float* __restrict__ b_o,
                      float* __restrict__ out_c) {
    int b = blockIdx.y;
    int o = blockIdx.x * 128 + threadIdx.x;
    __shared__ float cs[En];
    for (int e = threadIdx.x; e < En; e += 128) {
        float s = 0.0f;
#pragma unroll
        for (int ch = 0; ch < TC_CHUNKS; ch++)
            s += g_cpart[((size_t)b * TC_CHUNKS + ch) * En + e];
        cs[e] = s;
    }
    __syncthreads();
    float acc = b_o[o];
#pragma unroll 8
    for (int e = 0; e < En; e++)
        acc = fmaf(cs[e], W_o[(size_t)e * On + o], acc);
    out_c[(size_t)b * On + o] = acc;
}

// ---------------- launch ----------------
extern "C" void kernel_launch(void* const* d_in, const int* in_sizes, int n_in,
                              void* d_out, int out_size) {
    const float* enc      = (const float*)d_in[0];
    const float* dec_z    = (const float*)d_in[2];
    const float* att_prev = (const float*)d_in[3];
    const float* W_enc    = (const float*)d_in[4];
    const float* b_enc    = (const float*)d_in[5];
    const float* W_dec    = (const float*)d_in[6];
    const float* W_att    = (const float*)d_in[7];
    const float* conv_w   = (const float*)d_in[8];
    const float* gvec     = (const float*)d_in[9];
    const float* W_o      = (const float*)d_in[10];
    const float* b_o      = (const float*)d_in[11];

    float* out   = (float*)d_out;
    float* out_c = out;            // [B, O]
    float* out_w = out + Bn * On;  // [B, T]

    cudaFuncSetAttribute(k_gemm_e, cudaFuncAttributeMaxDynamicSharedMemorySize, SMEM_GEMM);

    k_prep_b<<<dim3(16, 16), dim3(32, 8)>>>(W_enc);
    k_dec<<<dim3(4, Bn), 128>>>(dec_z, W_dec, b_enc);
    k_conv<<<dim3(12, Bn), 160>>>(att_prev, conv_w);
    k_gemm_e<<<dim3(NTILES, MTILES), 256, SMEM_GEMM>>>(enc, W_att, gvec);
    k_softmax<<<Bn, 512>>>(out_w);
    k_ctx<<<dim3(TC_CHUNKS, Bn), 512>>>(enc, out_w);
    k_out<<<dim3(On / 128, Bn), 128>>>(W_o, b_o, out_c);
}